// round 1
// baseline (speedup 1.0000x reference)
#include <cuda_runtime.h>
#include <math.h>

#define Bc   8
#define Cc   48
#define Nn   4096
#define KK   9
#define NBc  32768          // B*N
#define Ec   (Bc*Nn*KK)     // 294912

// -------- scratch (static device globals; no allocation) --------
__device__ float g_xn[NBc*Cc];      // normalized features, node-major
__device__ float g_nodes[NBc*Cc];   // raw features, node-major
__device__ float g_sq[NBc];         // sum of squares of normalized row
__device__ int   g_nn[NBc*KK];      // knn indices (within batch, 0..N-1)
__device__ int   g_deg[NBc];
__device__ float g_dinv[NBc];
__device__ float g_tx1[NBc*Cc];

// faithful replication of jnp.linspace(0, 8, E).astype(int32):
// value_i = fl(fl(i) * fl(8/294911)), truncated toward zero.
__device__ __forceinline__ int edge_count(int i) {
    const float STEP = 8.0f / 294911.0f;
    return (int)((float)i * STEP);
}

// ---------------- prep: transpose + normalize ----------------
__global__ void prep_kernel(const float* __restrict__ x) {
    int node = blockIdx.x * blockDim.x + threadIdx.x;
    if (node >= NBc) return;
    int b = node >> 12, n = node & (Nn - 1);
    const float* xb = x + (size_t)b * Cc * Nn + n;
    float v[Cc];
    float ss = 0.f;
#pragma unroll
    for (int c = 0; c < Cc; c++) { v[c] = xb[c * Nn]; ss += v[c] * v[c]; }
    float m = fmaxf(sqrtf(ss), 1e-12f);
    float sq = 0.f;
#pragma unroll
    for (int c = 0; c < Cc; c++) {
        float xv = v[c] / m;
        g_xn[node * Cc + c]    = xv;
        g_nodes[node * Cc + c] = v[c];
        sq += xv * xv;
    }
    g_sq[node]  = sq;
    g_deg[node] = 0;
}

// ---------------- KNN: tiled distances + fused top-9 ----------------
#define QT 64
#define MT 64
#define PITCH 49

__device__ __forceinline__ bool lex_less(float d1, int i1, float d2, int i2) {
    return (d1 < d2) || (d1 == d2 && i1 < i2);
}

__global__ __launch_bounds__(256) void knn_kernel() {
    __shared__ float qs[QT * PITCH];
    __shared__ float ms[MT * PITCH];
    __shared__ float sqm[MT];

    int t  = threadIdx.x;
    int tx = t & 15, ty = t >> 4;
    int b  = blockIdx.y;
    int qBase = blockIdx.x * QT;
    int nodeBase = b * Nn;

    // load query tile (64 rows x 48)
    for (int i = t; i < QT * 12; i += 256) {
        int row = i / 12, v = i % 12;
        float4 f = *(const float4*)&g_xn[(nodeBase + qBase + row) * Cc + v * 4];
        float* d = &qs[row * PITCH + v * 4];
        d[0] = f.x; d[1] = f.y; d[2] = f.z; d[3] = f.w;
    }
    float sqq[4];
#pragma unroll
    for (int r = 0; r < 4; r++) sqq[r] = g_sq[nodeBase + qBase + ty * 4 + r];

    float dl[4][KK]; int il[4][KK];
#pragma unroll
    for (int r = 0; r < 4; r++)
#pragma unroll
        for (int s = 0; s < KK; s++) { dl[r][s] = 3.4e38f; il[r][s] = 0x7fffffff; }

    for (int mb = 0; mb < Nn; mb += MT) {
        __syncthreads();
        for (int i = t; i < MT * 12; i += 256) {
            int row = i / 12, v = i % 12;
            float4 f = *(const float4*)&g_xn[(nodeBase + mb + row) * Cc + v * 4];
            float* d = &ms[row * PITCH + v * 4];
            d[0] = f.x; d[1] = f.y; d[2] = f.z; d[3] = f.w;
        }
        if (t < MT) sqm[t] = g_sq[nodeBase + mb + t];
        __syncthreads();

        float acc[4][4];
#pragma unroll
        for (int r = 0; r < 4; r++)
#pragma unroll
            for (int c = 0; c < 4; c++) acc[r][c] = 0.f;

#pragma unroll 8
        for (int k = 0; k < Cc; k++) {
            float qv[4], mv[4];
#pragma unroll
            for (int r = 0; r < 4; r++) qv[r] = qs[(ty * 4 + r) * PITCH + k];
#pragma unroll
            for (int c = 0; c < 4; c++) mv[c] = ms[(tx * 4 + c) * PITCH + k];
#pragma unroll
            for (int r = 0; r < 4; r++)
#pragma unroll
                for (int c = 0; c < 4; c++)
                    acc[r][c] = fmaf(qv[r], mv[c], acc[r][c]);
        }

#pragma unroll
        for (int r = 0; r < 4; r++)
#pragma unroll
            for (int c = 0; c < 4; c++) {
                int   mi = mb + tx * 4 + c;
                float d  = (sqq[r] + sqm[tx * 4 + c]) - 2.f * acc[r][c];
                if (lex_less(d, mi, dl[r][KK - 1], il[r][KK - 1])) {
                    dl[r][KK - 1] = d; il[r][KK - 1] = mi;
#pragma unroll
                    for (int s = KK - 1; s > 0; --s) {
                        bool sw = lex_less(dl[r][s], il[r][s], dl[r][s - 1], il[r][s - 1]);
                        if (sw) {
                            float td = dl[r][s]; dl[r][s] = dl[r][s - 1]; dl[r][s - 1] = td;
                            int   ti = il[r][s]; il[r][s] = il[r][s - 1]; il[r][s - 1] = ti;
                        }
                    }
                }
            }
    }

    // butterfly merge across the 16 threads sharing each query-row group
#pragma unroll
    for (int delta = 1; delta <= 8; delta <<= 1) {
#pragma unroll
        for (int r = 0; r < 4; r++) {
            float od[KK]; int oi[KK];
#pragma unroll
            for (int s = 0; s < KK; s++) {
                od[s] = __shfl_xor_sync(0xffffffffu, dl[r][s], delta);
                oi[s] = __shfl_xor_sync(0xffffffffu, il[r][s], delta);
            }
#pragma unroll
            for (int s = 0; s < KK; s++) {
                float d = od[s]; int mi = oi[s];
                if (lex_less(d, mi, dl[r][KK - 1], il[r][KK - 1])) {
                    dl[r][KK - 1] = d; il[r][KK - 1] = mi;
#pragma unroll
                    for (int s2 = KK - 1; s2 > 0; --s2) {
                        bool sw = lex_less(dl[r][s2], il[r][s2], dl[r][s2 - 1], il[r][s2 - 1]);
                        if (sw) {
                            float td = dl[r][s2]; dl[r][s2] = dl[r][s2 - 1]; dl[r][s2 - 1] = td;
                            int   ti = il[r][s2]; il[r][s2] = il[r][s2 - 1]; il[r][s2 - 1] = ti;
                        }
                    }
                }
            }
        }
    }

    if (tx == 0) {
#pragma unroll
        for (int r = 0; r < 4; r++) {
            int row = nodeBase + qBase + ty * 4 + r;
#pragma unroll
            for (int s = 0; s < KK; s++) g_nn[row * KK + s] = il[r][s];
        }
    }
}

// ---------------- degree (int atomics: deterministic) ----------------
__global__ void deg_kernel() {
    int i = blockIdx.x * blockDim.x + threadIdx.x;
    if (i >= Ec) return;
    int cnt  = edge_count(i);
    int rown = i / KK;              // b*N + n
    int n    = rown & (Nn - 1);
    int m    = g_nn[i];
    int src  = m + cnt * Nn;
    int dst  = n + cnt * Nn;
    if (src < NBc && dst < NBc) atomicAdd(&g_deg[src], 1);
}

__global__ void dinv_kernel() {
    int i = blockIdx.x * blockDim.x + threadIdx.x;
    if (i >= NBc) return;
    int d = g_deg[i];
    g_dinv[i] = (d > 0) ? (1.0f / sqrtf((float)d)) : 0.0f;
}

// ---------------- Tx1: deterministic gather-side aggregation ----------------
// dst = q*N + n receives only from center rows (b', n) with b' in {q-1, q}
// whose edge index i has count(i)==q (linspace-count structure).
__global__ void tx1_kernel() {
    int flat = blockIdx.x * blockDim.x + threadIdx.x;
    if (flat >= NBc * Cc) return;
    int d  = flat / Cc, ch = flat % Cc;
    int q  = d >> 12, n = d & (Nn - 1);
    float dv = g_dinv[d];
    float acc = 0.f;
#pragma unroll
    for (int bb = 0; bb < 2; bb++) {
        int bp = q - 1 + bb;
        if (bp < 0 || bp >= Bc) continue;
        int ibase = (bp * Nn + n) * KK;
#pragma unroll
        for (int j = 0; j < KK; j++) {
            int i = ibase + j;
            if (edge_count(i) == q) {
                int src = g_nn[i] + q * Nn;   // always < NB since q <= 7
                acc = fmaf(-dv * g_dinv[src], g_nodes[src * Cc + ch], acc);
            }
        }
    }
    g_tx1[flat] = acc;
}

// ---------------- epilogue: out = nodes@W0 + Tx1@W1 + bias ----------------
__global__ void out_kernel(const float* __restrict__ W0, const float* __restrict__ W1,
                           const float* __restrict__ bias, float* __restrict__ out) {
    __shared__ float sW0[Cc * Cc], sW1[Cc * Cc], sb[Cc];
    int t = threadIdx.x;
    for (int i = t; i < Cc * Cc; i += blockDim.x) { sW0[i] = W0[i]; sW1[i] = W1[i]; }
    if (t < Cc) sb[t] = bias[t];
    __syncthreads();
    int flat = blockIdx.x * blockDim.x + t;
    if (flat >= NBc * Cc) return;
    int d = flat / Cc, co = flat % Cc;
    const float* nrow = &g_nodes[d * Cc];
    const float* trow = &g_tx1[d * Cc];
    float acc = sb[co];
#pragma unroll
    for (int k = 0; k < Cc; k++)
        acc = fmaf(nrow[k], sW0[k * Cc + co], fmaf(trow[k], sW1[k * Cc + co], acc));
    out[flat] = acc;
}

// ---------------- launch ----------------
extern "C" void kernel_launch(void* const* d_in, const int* in_sizes, int n_in,
                              void* d_out, int out_size) {
    const float* x    = (const float*)d_in[0];
    const float* W0   = (const float*)d_in[1];
    const float* W1   = (const float*)d_in[2];
    const float* bias = (const float*)d_in[3];
    float* out = (float*)d_out;
    (void)in_sizes; (void)n_in; (void)out_size;

    prep_kernel<<<NBc / 256, 256>>>(x);
    dim3 gknn(Nn / QT, Bc);
    knn_kernel<<<gknn, 256>>>();
    deg_kernel<<<(Ec + 255) / 256, 256>>>();
    dinv_kernel<<<NBc / 256, 256>>>();
    tx1_kernel<<<(NBc * Cc) / 256, 256>>>();
    out_kernel<<<(NBc * Cc) / 256, 256>>>(W0, W1, bias, out);
}

// round 4
// speedup vs baseline: 1.2525x; 1.2525x over previous
#include <cuda_runtime.h>
#include <math.h>

#define Bc   8
#define Cc   48
#define Nn   4096
#define KK   9
#define NBc  32768          // B*N
#define Ec   (Bc*Nn*KK)     // 294912

// -------- scratch (static device globals; no allocation) --------
__device__ float g_xn[NBc*Cc];      // normalized features, node-major
__device__ float g_nodes[NBc*Cc];   // raw features, node-major
__device__ float g_sq[NBc];         // sum of squares of normalized row
__device__ int   g_nn[NBc*KK];      // knn indices (within batch, 0..N-1)
__device__ int   g_deg[NBc];
__device__ float g_dinv[NBc];
__device__ float g_tx1[NBc*Cc];

// faithful replication of jnp.linspace(0, 8, E).astype(int32):
// value_i = fl(fl(i) * fl(8/294911)), truncated toward zero.
__device__ __forceinline__ int edge_count(int i) {
    const float STEP = 8.0f / 294911.0f;
    return (int)((float)i * STEP);
}

// ---------------- prep: transpose + normalize ----------------
__global__ void prep_kernel(const float* __restrict__ x) {
    int node = blockIdx.x * blockDim.x + threadIdx.x;
    if (node >= NBc) return;
    int b = node >> 12, n = node & (Nn - 1);
    const float* xb = x + (size_t)b * Cc * Nn + n;
    float v[Cc];
    float ss = 0.f;
#pragma unroll
    for (int c = 0; c < Cc; c++) { v[c] = xb[c * Nn]; ss += v[c] * v[c]; }
    float m = fmaxf(sqrtf(ss), 1e-12f);
    float sq = 0.f;
#pragma unroll
    for (int c = 0; c < Cc; c++) {
        float xv = v[c] / m;
        g_xn[node * Cc + c]    = xv;
        g_nodes[node * Cc + c] = v[c];
        sq += xv * xv;
    }
    g_sq[node]  = sq;
    g_deg[node] = 0;
}

// ---------------- KNN: tiled distances + fused top-9 (u64 keys) ----------------
// Block: 256 threads. Each thread: 1 query row x 16 candidate cols.
// QT=64 query rows per block, MT=64 candidate tile.
#define QT 64
#define MT 64
#define PITCH 64   // words per k-row in the k-major smem tiles

// monotone float->uint map: preserves < ordering for all finite floats
__device__ __forceinline__ unsigned int fmono(float d) {
    unsigned int u = __float_as_uint(d);
    return (u & 0x80000000u) ? ~u : (u | 0x80000000u);
}
__device__ __forceinline__ float fmono_inv(unsigned int u) {
    return __uint_as_float((u & 0x80000000u) ? (u ^ 0x80000000u) : ~u);
}

__global__ __launch_bounds__(256, 4) void knn_kernel() {
    __shared__ float qs[Cc * PITCH];   // qs[k*PITCH + r]  (12.3 KB)
    __shared__ float ms[Cc * PITCH];   // ms[k*PITCH + c]  (12.3 KB)
    __shared__ float sqm[MT];

    int t    = threadIdx.x;
    int row  = t >> 2;            // 0..63
    int cseg = (t & 3) * 16;      // 0,16,32,48
    int b    = blockIdx.y;
    int qBase = blockIdx.x * QT;
    int nodeBase = b * Nn;

    // load query tile, transposed to k-major
    for (int i = t; i < QT * 12; i += 256) {
        int r = i / 12, v = i % 12;
        float4 f = *(const float4*)&g_xn[(nodeBase + qBase + r) * Cc + v * 4];
        qs[(v * 4 + 0) * PITCH + r] = f.x;
        qs[(v * 4 + 1) * PITCH + r] = f.y;
        qs[(v * 4 + 2) * PITCH + r] = f.z;
        qs[(v * 4 + 3) * PITCH + r] = f.w;
    }
    float sqq = g_sq[nodeBase + qBase + row];

    // sentinel: (d=+INF, idx=0xFFFFFFFF)  -> hi = fmono(+INF) = 0xFF800000
    unsigned long long lst[KK];
#pragma unroll
    for (int s = 0; s < KK; s++) lst[s] = 0xFF800000FFFFFFFFULL;
    float thr = __int_as_float(0x7F800000);   // +INF

    for (int mb = 0; mb < Nn; mb += MT) {
        __syncthreads();
        for (int i = t; i < MT * 12; i += 256) {
            int r = i / 12, v = i % 12;
            float4 f = *(const float4*)&g_xn[(nodeBase + mb + r) * Cc + v * 4];
            ms[(v * 4 + 0) * PITCH + r] = f.x;
            ms[(v * 4 + 1) * PITCH + r] = f.y;
            ms[(v * 4 + 2) * PITCH + r] = f.z;
            ms[(v * 4 + 3) * PITCH + r] = f.w;
        }
        if (t < MT) sqm[t] = g_sq[nodeBase + mb + t];
        __syncthreads();

        float acc[16];
#pragma unroll
        for (int j = 0; j < 16; j++) acc[j] = 0.f;

#pragma unroll 8
        for (int k = 0; k < Cc; k++) {
            float  qv = qs[k * PITCH + row];
            const float* mrow = &ms[k * PITCH + cseg];
            float4 m0 = *(const float4*)(mrow + 0);
            float4 m1 = *(const float4*)(mrow + 4);
            float4 m2 = *(const float4*)(mrow + 8);
            float4 m3 = *(const float4*)(mrow + 12);
            acc[0]  = fmaf(qv, m0.x, acc[0]);  acc[1]  = fmaf(qv, m0.y, acc[1]);
            acc[2]  = fmaf(qv, m0.z, acc[2]);  acc[3]  = fmaf(qv, m0.w, acc[3]);
            acc[4]  = fmaf(qv, m1.x, acc[4]);  acc[5]  = fmaf(qv, m1.y, acc[5]);
            acc[6]  = fmaf(qv, m1.z, acc[6]);  acc[7]  = fmaf(qv, m1.w, acc[7]);
            acc[8]  = fmaf(qv, m2.x, acc[8]);  acc[9]  = fmaf(qv, m2.y, acc[9]);
            acc[10] = fmaf(qv, m2.z, acc[10]); acc[11] = fmaf(qv, m2.w, acc[11]);
            acc[12] = fmaf(qv, m3.x, acc[12]); acc[13] = fmaf(qv, m3.y, acc[13]);
            acc[14] = fmaf(qv, m3.z, acc[14]); acc[15] = fmaf(qv, m3.w, acc[15]);
        }

#pragma unroll
        for (int j = 0; j < 16; j++) {
            float d = (sqq + sqm[cseg + j]) - 2.f * acc[j];
            if (d <= thr) {
                int mi = mb + cseg + j;
                unsigned long long key =
                    ((unsigned long long)fmono(d) << 32) | (unsigned int)mi;
                if (key < lst[KK - 1]) {
                    lst[KK - 1] = key;
#pragma unroll
                    for (int s = KK - 1; s > 0; --s) {
                        if (lst[s] < lst[s - 1]) {
                            unsigned long long tmp = lst[s];
                            lst[s] = lst[s - 1]; lst[s - 1] = tmp;
                        }
                    }
                    thr = fmono_inv((unsigned int)(lst[KK - 1] >> 32));
                }
            }
        }
    }

    // butterfly merge across the 4 threads (quad) sharing this query row
#pragma unroll
    for (int delta = 1; delta <= 2; delta <<= 1) {
        unsigned long long other[KK];
#pragma unroll
        for (int s = 0; s < KK; s++)
            other[s] = __shfl_xor_sync(0xffffffffu, lst[s], delta);
#pragma unroll
        for (int s = 0; s < KK; s++) {
            if (other[s] < lst[KK - 1]) {
                lst[KK - 1] = other[s];
#pragma unroll
                for (int s2 = KK - 1; s2 > 0; --s2) {
                    if (lst[s2] < lst[s2 - 1]) {
                        unsigned long long tmp = lst[s2];
                        lst[s2] = lst[s2 - 1]; lst[s2 - 1] = tmp;
                    }
                }
            }
        }
    }

    if ((t & 3) == 0) {
        int nrow = nodeBase + qBase + row;
#pragma unroll
        for (int s = 0; s < KK; s++)
            g_nn[nrow * KK + s] = (int)(unsigned int)(lst[s] & 0xFFFFFFFFu);
    }
}

// ---------------- degree (int atomics: deterministic) ----------------
__global__ void deg_kernel() {
    int i = blockIdx.x * blockDim.x + threadIdx.x;
    if (i >= Ec) return;
    int cnt  = edge_count(i);
    int rown = i / KK;              // b*N + n
    int n    = rown & (Nn - 1);
    int m    = g_nn[i];
    int src  = m + cnt * Nn;
    int dst  = n + cnt * Nn;
    if (src < NBc && dst < NBc) atomicAdd(&g_deg[src], 1);
}

__global__ void dinv_kernel() {
    int i = blockIdx.x * blockDim.x + threadIdx.x;
    if (i >= NBc) return;
    int d = g_deg[i];
    g_dinv[i] = (d > 0) ? (1.0f / sqrtf((float)d)) : 0.0f;
}

// ---------------- Tx1: deterministic gather-side aggregation ----------------
// dst = q*N + n receives only from center rows (b', n) with b' in {q-1, q}
// whose edge index i has count(i)==q (linspace-count structure).
__global__ void tx1_kernel() {
    int flat = blockIdx.x * blockDim.x + threadIdx.x;
    if (flat >= NBc * Cc) return;
    int d  = flat / Cc, ch = flat % Cc;
    int q  = d >> 12, n = d & (Nn - 1);
    float dv = g_dinv[d];
    float acc = 0.f;
#pragma unroll
    for (int bb = 0; bb < 2; bb++) {
        int bp = q - 1 + bb;
        if (bp < 0 || bp >= Bc) continue;
        int ibase = (bp * Nn + n) * KK;
#pragma unroll
        for (int j = 0; j < KK; j++) {
            int i = ibase + j;
            if (edge_count(i) == q) {
                int src = g_nn[i] + q * Nn;   // always < NB since q <= 7
                acc = fmaf(-dv * g_dinv[src], g_nodes[src * Cc + ch], acc);
            }
        }
    }
    g_tx1[flat] = acc;
}

// ---------------- epilogue: out = nodes@W0 + Tx1@W1 + bias ----------------
__global__ void out_kernel(const float* __restrict__ W0, const float* __restrict__ W1,
                           const float* __restrict__ bias, float* __restrict__ out) {
    __shared__ float sW0[Cc * Cc], sW1[Cc * Cc], sb[Cc];
    int t = threadIdx.x;
    for (int i = t; i < Cc * Cc; i += blockDim.x) { sW0[i] = W0[i]; sW1[i] = W1[i]; }
    if (t < Cc) sb[t] = bias[t];
    __syncthreads();
    int flat = blockIdx.x * blockDim.x + t;
    if (flat >= NBc * Cc) return;
    int d = flat / Cc, co = flat % Cc;
    const float* nrow = &g_nodes[d * Cc];
    const float* trow = &g_tx1[d * Cc];
    float acc = sb[co];
#pragma unroll
    for (int k = 0; k < Cc; k++)
        acc = fmaf(nrow[k], sW0[k * Cc + co], fmaf(trow[k], sW1[k * Cc + co], acc));
    out[flat] = acc;
}

// ---------------- launch ----------------
extern "C" void kernel_launch(void* const* d_in, const int* in_sizes, int n_in,
                              void* d_out, int out_size) {
    const float* x    = (const float*)d_in[0];
    const float* W0   = (const float*)d_in[1];
    const float* W1   = (const float*)d_in[2];
    const float* bias = (const float*)d_in[3];
    float* out = (float*)d_out;
    (void)in_sizes; (void)n_in; (void)out_size;

    prep_kernel<<<NBc / 256, 256>>>(x);
    dim3 gknn(Nn / QT, Bc);
    knn_kernel<<<gknn, 256>>>();
    deg_kernel<<<(Ec + 255) / 256, 256>>>();
    dinv_kernel<<<NBc / 256, 256>>>();
    tx1_kernel<<<(NBc * Cc) / 256, 256>>>();
    out_kernel<<<(NBc * Cc) / 256, 256>>>(W0, W1, bias, out);
}